// round 13
// baseline (speedup 1.0000x reference)
#include <cuda_runtime.h>
#include <cuda_bf16.h>
#include <cuda_fp16.h>
#include <math.h>
#include <stdint.h>

// Problem constants
#define BB   2
#define SS   1024
#define PP   1024
#define TT   (PP + SS)
#define HH   4096
#define NQ   32
#define NKV  8
#define DD   128
#define QKVN ((NQ + 2 * NKV) * DD)   // 6144
#define SCALE 0.08838834764831845f   // 1/sqrt(128)

// ---------------------------------------------------------------------------
// Scratch (device globals: no allocation allowed)
// ---------------------------------------------------------------------------
__device__ float g_qkv[BB * SS * QKVN];
__device__ __half g_hid[BB * SS * HH];
__device__ __half g_wqkv[(size_t)QKVN * HH];         // transposed [N,K]
__device__ __half g_wo[(size_t)HH * HH];             // transposed [N,K]
__device__ __half g_attn_h[BB * SS * NQ * DD];
__device__ __half g_attn_l[BB * SS * NQ * DD];
__device__ __half g_q_f[(size_t)BB * NQ * SS * DD];
__device__ __half g_k_f[(size_t)BB * NKV * TT * DD];
__device__ __half g_v_f[(size_t)BB * NKV * TT * DD];

// ---------------------------------------------------------------------------
// Low-level helpers (plain sm_80+ ISA)
// ---------------------------------------------------------------------------
__device__ __forceinline__ uint32_t smem_u32(const void* p) {
    uint32_t a;
    asm("{ .reg .u64 t; cvta.to.shared.u64 t, %1; cvt.u32.u64 %0, t; }"
        : "=r"(a) : "l"(p));
    return a;
}
__device__ __forceinline__ void cp16(uint32_t dst, const void* src) {
    asm volatile("cp.async.cg.shared.global [%0], [%1], 16;"
                 :: "r"(dst), "l"(src));
}
__device__ __forceinline__ void ldsm4(uint32_t* r, uint32_t a) {
    asm volatile("ldmatrix.sync.aligned.m8n8.x4.shared.b16 {%0,%1,%2,%3}, [%4];"
                 : "=r"(r[0]), "=r"(r[1]), "=r"(r[2]), "=r"(r[3]) : "r"(a));
}
__device__ __forceinline__ void ldsm4t(uint32_t* r, uint32_t a) {
    asm volatile("ldmatrix.sync.aligned.m8n8.x4.trans.shared.b16 {%0,%1,%2,%3}, [%4];"
                 : "=r"(r[0]), "=r"(r[1]), "=r"(r[2]), "=r"(r[3]) : "r"(a));
}
__device__ __forceinline__ void mma16816h(float* c, const uint32_t* a,
                                          const uint32_t b0, const uint32_t b1) {
    asm volatile(
        "mma.sync.aligned.m16n8k16.row.col.f32.f16.f16.f32 "
        "{%0,%1,%2,%3}, {%4,%5,%6,%7}, {%8,%9}, {%0,%1,%2,%3};"
        : "+f"(c[0]), "+f"(c[1]), "+f"(c[2]), "+f"(c[3])
        : "r"(a[0]), "r"(a[1]), "r"(a[2]), "r"(a[3]), "r"(b0), "r"(b1));
}

// ---------------------------------------------------------------------------
// fp32 -> fp16 convert (GEMM1 activations)
// ---------------------------------------------------------------------------
__global__ void conv_f16(const float* __restrict__ x,
                         __half* __restrict__ xo, int n)
{
    int i = blockIdx.x * blockDim.x + threadIdx.x;
    if (i >= n) return;
    xo[i] = __float2half(x[i]);
}

// fp32 [R,C] -> fp16 transposed [C,R] (weights)
__global__ void trans_f16(const float* __restrict__ x,
                          __half* __restrict__ xo, int R, int C)
{
    __shared__ float t[32][33];
    int r0 = blockIdx.y * 32, c0 = blockIdx.x * 32;
    int tx = threadIdx.x, ty = threadIdx.y;
#pragma unroll
    for (int j = 0; j < 4; j++)
        t[ty + 8 * j][tx] = x[(size_t)(r0 + ty + 8 * j) * C + c0 + tx];
    __syncthreads();
#pragma unroll
    for (int j = 0; j < 4; j++)
        xo[(size_t)(c0 + ty + 8 * j) * R + r0 + tx] = __float2half(t[tx][ty + 8 * j]);
}

// ---------------------------------------------------------------------------
// fp16 single-pass GEMM (QKV): 128x256x128 block tile (BK=128 as two 64-wide
// sub-tiles), 8 warps, 2-stage cp.async pipeline, reg double-buffered frags.
// ---------------------------------------------------------------------------
#define X1_STAGE 98304                  // A0 16K | A1 16K | B0 32K | B1 32K
#define GEMM1_SMEM (2 * X1_STAGE)       // 196608

#define LOAD_STAGE1(c, s) do {                                               \
    int _k0 = (c) * 128;                                                     \
    uint32_t _stb = smb + (s) * X1_STAGE;                                    \
    _Pragma("unroll")                                                        \
    for (int _i = 0; _i < 8; _i++) {        /* A: 2048 16B chunks */         \
        int _id = tid + _i * 256;                                            \
        int _half = _id >> 10, _rid = _id & 1023;                            \
        int _row = _rid >> 3, _ch = _rid & 7;                                \
        uint32_t _sw = (_row << 7) + ((_ch ^ (_row & 7)) << 4);              \
        cp16(_stb + _half * 16384 + _sw,                                     \
             srcA + (size_t)_row * K + _k0 + _half * 64 + _ch * 8);          \
    }                                                                        \
    _Pragma("unroll")                                                        \
    for (int _i = 0; _i < 16; _i++) {       /* B: 4096 16B chunks */         \
        int _id = tid + _i * 256;                                            \
        int _half = _id >> 11, _rid = _id & 2047;                            \
        int _row = _rid >> 3, _ch = _rid & 7;                                \
        uint32_t _sw = (_row << 7) + ((_ch ^ (_row & 7)) << 4);              \
        cp16(_stb + 32768 + _half * 32768 + _sw,                             \
             srcB + (size_t)_row * K + _k0 + _half * 64 + _ch * 8);          \
    }                                                                        \
    asm volatile("cp.async.commit_group;");                                  \
} while (0)

__global__ __launch_bounds__(256, 1) void gemm_f16x1(
    const __half* __restrict__ A, const __half* __restrict__ B,
    float* __restrict__ C, int M, int N, int K)
{
    extern __shared__ char sm[];
    const uint32_t smb = smem_u32(sm);
    const int tid = threadIdx.x;
    const int wid = tid >> 5, lane = tid & 31;
    const int bm = blockIdx.y * 128, bn = blockIdx.x * 256;
    const int wm = (wid & 1) * 64, wn = (wid >> 1) * 64;

    const __half* srcA = A + (size_t)bm * K;
    const __half* srcB = B + (size_t)bn * K;

    uint32_t arb[4], brb[4];
    int rswA[4], rswB[4];
#pragma unroll
    for (int mi = 0; mi < 4; mi++) {
        int row = wm + mi * 16 + (lane & 15);
        arb[mi] = (uint32_t)(row << 7);
        rswA[mi] = row & 7;
    }
#pragma unroll
    for (int ni = 0; ni < 4; ni++) {
        int row = wn + ni * 16 + (lane & 15);
        brb[ni] = (uint32_t)(row << 7);
        rswB[ni] = row & 7;
    }

    float acc[4][8][4];
#pragma unroll
    for (int i = 0; i < 4; i++)
#pragma unroll
        for (int j = 0; j < 8; j++)
#pragma unroll
            for (int e = 0; e < 4; e++) acc[i][j][e] = 0.f;

    const int NC = K / 128;
    LOAD_STAGE1(0, 0);

    uint32_t ah[2][4][4], bh[2][4][4];
    for (int c = 0; c < NC; c++) {
        const int s = c & 1;
        if (c + 1 < NC) {
            LOAD_STAGE1(c + 1, s ^ 1);
            asm volatile("cp.async.wait_group 1;");
        } else {
            asm volatile("cp.async.wait_group 0;");
        }
        __syncthreads();

        const uint32_t base = smb + s * X1_STAGE;
        // prefetch ks=0 (half 0)
        {
            const int c0 = (lane >> 4);
#pragma unroll
            for (int mi = 0; mi < 4; mi++)
                ldsm4(ah[0][mi], base + arb[mi] + ((c0 ^ rswA[mi]) << 4));
#pragma unroll
            for (int ni = 0; ni < 4; ni++)
                ldsm4(bh[0][ni], base + 32768 + brb[ni] + ((c0 ^ rswB[ni]) << 4));
        }
#pragma unroll
        for (int ks = 0; ks < 8; ks++) {
            const int cur = ks & 1, nxt = cur ^ 1;
            if (ks < 7) {
                const int h2 = (ks + 1) >> 2;
                const int c0 = ((ks + 1) & 3) * 2 + (lane >> 4);
                const uint32_t ab = base + h2 * 16384;
                const uint32_t bb = base + 32768 + h2 * 32768;
#pragma unroll
                for (int mi = 0; mi < 4; mi++)
                    ldsm4(ah[nxt][mi], ab + arb[mi] + ((c0 ^ rswA[mi]) << 4));
#pragma unroll
                for (int ni = 0; ni < 4; ni++)
                    ldsm4(bh[nxt][ni], bb + brb[ni] + ((c0 ^ rswB[ni]) << 4));
            }
#pragma unroll
            for (int mi = 0; mi < 4; mi++)
#pragma unroll
                for (int ni = 0; ni < 4; ni++)
#pragma unroll
                    for (int sel = 0; sel < 2; sel++)
                        mma16816h(acc[mi][ni * 2 + sel], ah[cur][mi],
                                  bh[cur][ni][sel], bh[cur][ni][sel + 2]);
        }
        __syncthreads();
    }

    const int g = lane >> 2, t = lane & 3;
#pragma unroll
    for (int mi = 0; mi < 4; mi++) {
#pragma unroll
        for (int nj = 0; nj < 8; nj++) {
            const float* a = acc[mi][nj];
            int row = bm + wm + mi * 16 + g;
            int col = bn + wn + nj * 8 + t * 2;
            *(float2*)&C[(size_t)row * N + col] = make_float2(a[0], a[1]);
            *(float2*)&C[(size_t)(row + 8) * N + col] = make_float2(a[2], a[3]);
        }
    }
}

// ---------------------------------------------------------------------------
// fp16x2 GEMM (output projection) — unchanged from round 12.
// ---------------------------------------------------------------------------
#define AH_OFF 0
#define AL_OFF 16384
#define BH_OFF 32768
#define STAGE_B  65536
#define GEMM_SMEM (3 * STAGE_B)

#define LOAD_STAGE(c, s) do {                                              \
    int _k0 = (c) * 64;                                                    \
    uint32_t _stb = smb + (s) * STAGE_B;                                   \
    _Pragma("unroll")                                                      \
    for (int _i = 0; _i < 4; _i++) {                                       \
        int _id = tid + _i * 256;                                          \
        int _row = _id >> 3, _ch = _id & 7;                                \
        uint32_t _sw = (_row << 7) + ((_ch ^ (_row & 7)) << 4);            \
        const size_t _go = (size_t)_row * K + _k0 + _ch * 8;               \
        cp16(_stb + AH_OFF + _sw, srcAh + _go);                            \
        cp16(_stb + AL_OFF + _sw, srcAl + _go);                            \
    }                                                                      \
    _Pragma("unroll")                                                      \
    for (int _i = 0; _i < 8; _i++) {                                       \
        int _id = tid + _i * 256;                                          \
        int _row = _id >> 3, _ch = _id & 7;                                \
        uint32_t _sw = (_row << 7) + ((_ch ^ (_row & 7)) << 4);            \
        cp16(_stb + BH_OFF + _sw, srcB + (size_t)_row * K + _k0 + _ch * 8); \
    }                                                                      \
    asm volatile("cp.async.commit_group;");                                \
} while (0)

__global__ __launch_bounds__(256, 1) void gemm_f16x2(
    const __half* __restrict__ Ah, const __half* __restrict__ Al,
    const __half* __restrict__ B,
    float* __restrict__ C, int M, int N, int K)
{
    extern __shared__ char sm[];
    const uint32_t smb = smem_u32(sm);
    const int tid = threadIdx.x;
    const int wid = tid >> 5, lane = tid & 31;
    const int bm = blockIdx.y * 128, bn = blockIdx.x * 256;
    const int wm = (wid & 1) * 64, wn = (wid >> 1) * 64;

    const __half* srcAh = Ah + (size_t)bm * K;
    const __half* srcAl = Al + (size_t)bm * K;
    const __half* srcB  = B  + (size_t)bn * K;

    uint32_t arb[4], brb[4];
    int rswA[4], rswB[4];
#pragma unroll
    for (int mi = 0; mi < 4; mi++) {
        int row = wm + mi * 16 + (lane & 15);
        arb[mi] = (uint32_t)(row << 7);
        rswA[mi] = row & 7;
    }
#pragma unroll
    for (int ni = 0; ni < 4; ni++) {
        int row = wn + ni * 16 + (lane & 15);
        brb[ni] = (uint32_t)(row << 7);
        rswB[ni] = row & 7;
    }

    float acc[4][8][4];
#pragma unroll
    for (int i = 0; i < 4; i++)
#pragma unroll
        for (int j = 0; j < 8; j++)
#pragma unroll
            for (int e = 0; e < 4; e++) acc[i][j][e] = 0.f;

    const int NC = K / 64;
    LOAD_STAGE(0, 0);
    LOAD_STAGE(1, 1);

    uint32_t ah[2][4][4], bh[2][4][4], al[4][4];
    int sc = 0, sl = 2;
    for (int c = 0; c < NC; c++) {
        __syncthreads();
        if (c + 2 < NC) {
            LOAD_STAGE(c + 2, sl);
            asm volatile("cp.async.wait_group 2;");
        } else if (c + 1 < NC) {
            asm volatile("cp.async.wait_group 1;");
        } else {
            asm volatile("cp.async.wait_group 0;");
        }
        __syncthreads();

        const uint32_t base = smb + sc * STAGE_B;
        {
            const int c0 = (lane >> 4);
#pragma unroll
            for (int mi = 0; mi < 4; mi++)
                ldsm4(ah[0][mi], base + AH_OFF + arb[mi] + ((c0 ^ rswA[mi]) << 4));
#pragma unroll
            for (int ni = 0; ni < 4; ni++)
                ldsm4(bh[0][ni], base + BH_OFF + brb[ni] + ((c0 ^ rswB[ni]) << 4));
        }
#pragma unroll
        for (int ks = 0; ks < 4; ks++) {
            const int cur = ks & 1, nxt = cur ^ 1;
            const int c0c = ks * 2 + (lane >> 4);
#pragma unroll
            for (int mi = 0; mi < 4; mi++)
                ldsm4(al[mi], base + AL_OFF + arb[mi] + ((c0c ^ rswA[mi]) << 4));
            if (ks < 3) {
                const int c0n = (ks + 1) * 2 + (lane >> 4);
#pragma unroll
                for (int mi = 0; mi < 4; mi++)
                    ldsm4(ah[nxt][mi], base + AH_OFF + arb[mi] + ((c0n ^ rswA[mi]) << 4));
#pragma unroll
                for (int ni = 0; ni < 4; ni++)
                    ldsm4(bh[nxt][ni], base + BH_OFF + brb[ni] + ((c0n ^ rswB[ni]) << 4));
            }
#pragma unroll
            for (int mi = 0; mi < 4; mi++)
#pragma unroll
                for (int ni = 0; ni < 4; ni++)
#pragma unroll
                    for (int sel = 0; sel < 2; sel++)
                        mma16816h(acc[mi][ni * 2 + sel], ah[cur][mi],
                                  bh[cur][ni][sel], bh[cur][ni][sel + 2]);
#pragma unroll
            for (int mi = 0; mi < 4; mi++)
#pragma unroll
                for (int ni = 0; ni < 4; ni++)
#pragma unroll
                    for (int sel = 0; sel < 2; sel++)
                        mma16816h(acc[mi][ni * 2 + sel], al[mi],
                                  bh[cur][ni][sel], bh[cur][ni][sel + 2]);
        }
        sc = (sc == 2) ? 0 : sc + 1;
        sl = (sl == 2) ? 0 : sl + 1;
    }

    const int g = lane >> 2, t = lane & 3;
#pragma unroll
    for (int mi = 0; mi < 4; mi++) {
#pragma unroll
        for (int nj = 0; nj < 8; nj++) {
            const float* a = acc[mi][nj];
            int row = bm + wm + mi * 16 + g;
            int col = bn + wn + nj * 8 + t * 2;
            *(float2*)&C[(size_t)row * N + col] = make_float2(a[0], a[1]);
            *(float2*)&C[(size_t)(row + 8) * N + col] = make_float2(a[2], a[3]);
        }
    }
}

// ---------------------------------------------------------------------------
// Fused pre-pass (unchanged arithmetic)
// ---------------------------------------------------------------------------
#define NQTOT (BB * SS * NQ * 64)
#define KVTOT (BB * NKV * TT * 64)

__global__ void prep_qkv_f16(const float* __restrict__ qkv,
                             const float* __restrict__ kcache,
                             const float* __restrict__ vcache,
                             const float* __restrict__ cosb,
                             const float* __restrict__ sinb,
                             __half* __restrict__ qf,
                             __half* __restrict__ kf, __half* __restrict__ vf)
{
    int idx = blockIdx.x * blockDim.x + threadIdx.x;
    if (idx < NQTOT) {
        int d = idx & 63;
        int rest = idx >> 6;
        int h = rest % NQ;
        int s = (rest / NQ) % SS;
        int b = rest / (NQ * SS);
        const float* base = &qkv[((size_t)(b * SS + s)) * QKVN + h * DD];
        float x1 = base[d], x2 = base[d + 64];
        float c0 = cosb[s * DD + d],      s0 = sinb[s * DD + d];
        float c1 = cosb[s * DD + d + 64], s1 = sinb[s * DD + d + 64];
        size_t o = (((size_t)(b * NQ + h)) * SS + s) * DD + d;
        qf[o]      = __float2half((x1 * c0 - x2 * s0) * SCALE);
        qf[o + 64] = __float2half((x2 * c1 + x1 * s1) * SCALE);
        return;
    }
    idx -= NQTOT;
    if (idx >= KVTOT) return;
    int d = idx & 63;
    int rest = idx >> 6;
    int t = rest % TT;
    int kh = (rest / TT) % NKV;
    int b = rest / (TT * NKV);

    float k1, k2, v1, v2;
    if (t < PP) {
        size_t src = (((size_t)(b * PP + t)) * NKV + kh) * DD;
        k1 = kcache[src + d]; k2 = kcache[src + d + 64];
        v1 = vcache[src + d]; v2 = vcache[src + d + 64];
    } else {
        int s = t - PP;
        const float* base = &qkv[((size_t)(b * SS + s)) * QKVN];
        float x1 = base[(NQ + kh) * DD + d], x2 = base[(NQ + kh) * DD + d + 64];
        float c0 = cosb[s * DD + d],      s0 = sinb[s * DD + d];
        float c1 = cosb[s * DD + d + 64], s1 = sinb[s * DD + d + 64];
        k1 = x1 * c0 - x2 * s0;
        k2 = x2 * c1 + x1 * s1;
        v1 = base[(NQ + NKV + kh) * DD + d];
        v2 = base[(NQ + NKV + kh) * DD + d + 64];
    }
    size_t o = (((size_t)(b * NKV + kh)) * TT + t) * DD + d;
    kf[o]      = __float2half(k1);
    kf[o + 64] = __float2half(k2);
    vf[o]      = __float2half(v1);
    vf[o + 64] = __float2half(v2);
}

// ---------------------------------------------------------------------------
// Flash attention: 128-query tile, 8 warps, double-buffered KV tiles.
// fp16 single-pass QK and PV; epilogue emits fp16 hi/lo.
// ---------------------------------------------------------------------------
#define FA_SMEM (4 * 16384)   // 2 buffers x (K 16KB + V 16KB)

#define FLOADKV(kt, b) do {                                                  \
    const __half* _srcK = kf_g + kvb + (size_t)(kt) * 64 * DD;               \
    const __half* _srcV = vf_g + kvb + (size_t)(kt) * 64 * DD;               \
    uint32_t _kb = smb + (b) * 32768;                                        \
    _Pragma("unroll")                                                        \
    for (int _i = 0; _i < 4; _i++) {                                         \
        int _id = tid + _i * 256;                                            \
        int _r = _id >> 4, _ch = _id & 15;                                   \
        uint32_t _sw = _r * 256 + ((_ch ^ (_r & 7)) << 4);                   \
        cp16(_kb + _sw,         _srcK + _r * DD + _ch * 8);                  \
        cp16(_kb + 16384 + _sw, _srcV + _r * DD + _ch * 8);                  \
    }                                                                        \
    asm volatile("cp.async.commit_group;");                                  \
} while (0)

__global__ __launch_bounds__(256) void flash_mma(
    const __half* __restrict__ qf_g,
    const __half* __restrict__ kf_g,
    const __half* __restrict__ vf_g,
    __half* __restrict__ attnh, __half* __restrict__ attnl)
{
    extern __shared__ char sm[];
    const uint32_t smb = smem_u32(sm);
    const int tid = threadIdx.x, lane = tid & 31, w = tid >> 5;
    const int qi = blockIdx.x, h = blockIdx.y, b = blockIdx.z;
    const int sq0 = qi * 128;
    const int khd = h >> 2;
    const int g = lane >> 2, t4 = lane & 3;
    const int r0 = w * 16 + g, r1 = r0 + 8;

    uint32_t qf[8][4];
    {
        const __half* qb = qf_g + (((size_t)(b * NQ + h)) * SS + sq0) * DD;
#pragma unroll
        for (int ks = 0; ks < 8; ks++) {
            int c0 = ks * 16 + 2 * t4;
            qf[ks][0] = *(const uint32_t*)(qb + r0 * DD + c0);
            qf[ks][1] = *(const uint32_t*)(qb + r1 * DD + c0);
            qf[ks][2] = *(const uint32_t*)(qb + r0 * DD + c0 + 8);
            qf[ks][3] = *(const uint32_t*)(qb + r1 * DD + c0 + 8);
        }
    }

    uint32_t krb[4];
    int krsw[4];
#pragma unroll
    for (int kg = 0; kg < 4; kg++) {
        int r = kg * 16 + (lane & 15);
        krb[kg] = (uint32_t)(r * 256);
        krsw[kg] = r & 7;
    }

    float oacc[16][4];
#pragma unroll
    for (int i = 0; i < 16; i++)
#pragma unroll
        for (int j = 0; j < 4; j++) oacc[i][j] = 0.f;
    float m0 = -1e30f, m1 = -1e30f, l0 = 0.f, l1 = 0.f;

    const size_t kvb = ((size_t)(b * NKV + khd)) * TT * DD;
    const int nt = 2 * qi + 18;   // (PP + sq0 + 128)/64

    FLOADKV(0, 0);

    for (int kt = 0; kt < nt; kt++) {
        const int bf = kt & 1;
        if (kt + 1 < nt) {
            FLOADKV(kt + 1, bf ^ 1);
            asm volatile("cp.async.wait_group 1;");
        } else {
            asm volatile("cp.async.wait_group 0;");
        }
        __syncthreads();

        const uint32_t KB = smb + bf * 32768;
        const uint32_t VB = KB + 16384;

        // S = Q K^T with K-fragment double buffering
        float sacc[8][4];
#pragma unroll
        for (int j = 0; j < 8; j++)
#pragma unroll
            for (int e = 0; e < 4; e++) sacc[j][e] = 0.f;

        uint32_t kb[2][4][4];
        {
            const int c0 = (lane >> 4);
#pragma unroll
            for (int kg = 0; kg < 4; kg++)
                ldsm4(kb[0][kg], KB + krb[kg] + ((c0 ^ krsw[kg]) << 4));
        }
#pragma unroll
        for (int ks = 0; ks < 8; ks++) {
            const int cur = ks & 1, nxt = cur ^ 1;
            if (ks < 7) {
                const int c0 = (ks + 1) * 2 + (lane >> 4);
#pragma unroll
                for (int kg = 0; kg < 4; kg++)
                    ldsm4(kb[nxt][kg], KB + krb[kg] + ((c0 ^ krsw[kg]) << 4));
            }
#pragma unroll
            for (int kg = 0; kg < 4; kg++)
#pragma unroll
                for (int sel = 0; sel < 2; sel++)
                    mma16816h(sacc[kg * 2 + sel], qf[ks],
                              kb[cur][kg][sel], kb[cur][kg][sel + 2]);
        }

        // causal mask (last two tiles only)
        if (kt >= nt - 2) {
            const int kd = kt * 64 - PP - sq0;   // 0 or 64
#pragma unroll
            for (int j = 0; j < 8; j++) {
                int cb = j * 8 + 2 * t4 + kd;
                if (cb     > r0) sacc[j][0] = -1e30f;
                if (cb + 1 > r0) sacc[j][1] = -1e30f;
                if (cb     > r1) sacc[j][2] = -1e30f;
                if (cb + 1 > r1) sacc[j][3] = -1e30f;
            }
        }

        float mx0 = m0, mx1 = m1;
#pragma unroll
        for (int j = 0; j < 8; j++) {
            mx0 = fmaxf(mx0, fmaxf(sacc[j][0], sacc[j][1]));
            mx1 = fmaxf(mx1, fmaxf(sacc[j][2], sacc[j][3]));
        }
        mx0 = fmaxf(mx0, __shfl_xor_sync(0xffffffff, mx0, 1));
        mx0 = fmaxf(mx0, __shfl_xor_sync(0xffffffff, mx0, 2));
        mx1 = fmaxf(mx1, __shfl_xor_sync(0xffffffff, mx1, 1));
        mx1 = fmaxf(mx1, __shfl_xor_sync(0xffffffff, mx1, 2));
        float rs0 = __expf(m0 - mx0), rs1 = __expf(m1 - mx1);
        m0 = mx0; m1 = mx1;
        l0 *= rs0; l1 *= rs1;

        uint32_t pf[4][4];
#pragma unroll
        for (int j = 0; j < 8; j++) {
            float p0 = __expf(sacc[j][0] - m0);
            float p1 = __expf(sacc[j][1] - m0);
            float p2 = __expf(sacc[j][2] - m1);
            float p3 = __expf(sacc[j][3] - m1);
            l0 += p0 + p1; l1 += p2 + p3;
            int kk = j >> 1, u = (j & 1) * 2;
            __half2 hA = __float22half2_rn(make_float2(p0, p1));
            __half2 hB = __float22half2_rn(make_float2(p2, p3));
            pf[kk][u]     = *(uint32_t*)&hA;
            pf[kk][u + 1] = *(uint32_t*)&hB;
        }

#pragma unroll
        for (int i = 0; i < 16; i++) {
            oacc[i][0] *= rs0; oacc[i][1] *= rs0;
            oacc[i][2] *= rs1; oacc[i][3] *= rs1;
        }

        // O += P V with V-fragment double buffering
        uint32_t vfr[2][2][4];
        {
            int r = (lane & 15);
            int cA = (lane >> 4);
            int cB = 2 + (lane >> 4);
            ldsm4t(vfr[0][0], VB + r * 256 + ((cA ^ (r & 7)) << 4));
            ldsm4t(vfr[0][1], VB + r * 256 + ((cB ^ (r & 7)) << 4));
        }
#pragma unroll
        for (int idx = 0; idx < 16; idx++) {
            const int cur = idx & 1, nxt = cur ^ 1;
            const int kk = idx >> 2, dp = idx & 3;
            if (idx < 15) {
                const int kk2 = (idx + 1) >> 2, dp2 = (idx + 1) & 3;
                int r = kk2 * 16 + (lane & 15);
                int cA = dp2 * 4 + (lane >> 4);
                int cB = dp2 * 4 + 2 + (lane >> 4);
                ldsm4t(vfr[nxt][0], VB + r * 256 + ((cA ^ (r & 7)) << 4));
                ldsm4t(vfr[nxt][1], VB + r * 256 + ((cB ^ (r & 7)) << 4));
            }
            const int dg0 = dp * 2, dg1 = dp * 2 + 1;
            mma16816h(oacc[dg0 * 2],     pf[kk], vfr[cur][0][0], vfr[cur][0][1]);
            mma16816h(oacc[dg0 * 2 + 1], pf[kk], vfr[cur][0][2], vfr[cur][0][3]);
            mma16816h(oacc[dg1 * 2],     pf[kk], vfr[cur][1][0], vfr[cur][1][1]);
            mma16816h(oacc[dg1 * 2 + 1], pf[kk], vfr[cur][1][2], vfr[cur][1][3]);
        }
        __syncthreads();   // all warps done with buffer bf before reload
    }

    l0 += __shfl_xor_sync(0xffffffff, l0, 1);
    l0 += __shfl_xor_sync(0xffffffff, l0, 2);
    l1 += __shfl_xor_sync(0xffffffff, l1, 1);
    l1 += __shfl_xor_sync(0xffffffff, l1, 2);
    float inv0 = 1.f / l0, inv1 = 1.f / l1;

    size_t rowA = ((size_t)(b * SS + sq0 + r0)) * (NQ * DD) + h * DD;
    size_t rowB = ((size_t)(b * SS + sq0 + r1)) * (NQ * DD) + h * DD;
#pragma unroll
    for (int dt = 0; dt < 16; dt++) {
        int c = dt * 8 + 2 * t4;
        float v0 = oacc[dt][0] * inv0, v1 = oacc[dt][1] * inv0;
        float v2 = oacc[dt][2] * inv1, v3 = oacc[dt][3] * inv1;
        __half2 hA = __float22half2_rn(make_float2(v0, v1));
        float2 fA = __half22float2(hA);
        __half2 lA = __float22half2_rn(make_float2(v0 - fA.x, v1 - fA.y));
        __half2 hB = __float22half2_rn(make_float2(v2, v3));
        float2 fB = __half22float2(hB);
        __half2 lB = __float22half2_rn(make_float2(v2 - fB.x, v3 - fB.y));
        *(__half2*)&attnh[rowA + c] = hA;
        *(__half2*)&attnl[rowA + c] = lA;
        *(__half2*)&attnh[rowB + c] = hB;
        *(__half2*)&attnl[rowB + c] = lB;
    }
}

// ---------------------------------------------------------------------------
extern "C" void kernel_launch(void* const* d_in, const int* in_sizes, int n_in,
                              void* d_out, int out_size)
{
    const float* hidden = (const float*)d_in[0];
    const float* w_qkv  = (const float*)d_in[1];
    const float* w_o    = (const float*)d_in[2];
    const float* cosb   = (const float*)d_in[3];
    const float* sinb   = (const float*)d_in[4];
    const float* kc     = (const float*)d_in[5];
    const float* vc     = (const float*)d_in[6];
    float* out = (float*)d_out;

    float *qkv;
    __half *hidf, *wq, *wo, *ath, *atl, *qf, *kf, *vf;
    cudaGetSymbolAddress((void**)&qkv, g_qkv);
    cudaGetSymbolAddress((void**)&hidf, g_hid);
    cudaGetSymbolAddress((void**)&wq, g_wqkv);
    cudaGetSymbolAddress((void**)&wo, g_wo);
    cudaGetSymbolAddress((void**)&ath, g_attn_h);
    cudaGetSymbolAddress((void**)&atl, g_attn_l);
    cudaGetSymbolAddress((void**)&qf, g_q_f);
    cudaGetSymbolAddress((void**)&kf, g_k_f);
    cudaGetSymbolAddress((void**)&vf, g_v_f);

    cudaFuncSetAttribute(gemm_f16x1,
                         cudaFuncAttributeMaxDynamicSharedMemorySize, GEMM1_SMEM);
    cudaFuncSetAttribute(gemm_f16x2,
                         cudaFuncAttributeMaxDynamicSharedMemorySize, GEMM_SMEM);
    cudaFuncSetAttribute(flash_mma,
                         cudaFuncAttributeMaxDynamicSharedMemorySize, FA_SMEM);

    const int M = BB * SS;  // 2048

    // 0) activation convert + weight transposes
    {
        int n = M * HH;
        conv_f16<<<(n + 255) / 256, 256>>>(hidden, hidf, n);
        trans_f16<<<dim3(QKVN / 32, HH / 32), dim3(32, 8)>>>(w_qkv, wq, HH, QKVN);
        trans_f16<<<dim3(HH / 32, HH / 32), dim3(32, 8)>>>(w_o, wo, HH, HH);
    }
    // 1) QKV projection (fp16 single-pass, BK=128)
    gemm_f16x1<<<dim3(QKVN / 256, M / 128), 256, GEMM1_SMEM>>>(
        hidf, wq, qkv, M, QKVN, HH);
    // 2) fused pre-pass
    {
        int total = NQTOT + KVTOT;
        prep_qkv_f16<<<(total + 255) / 256, 256>>>(qkv, kc, vc, cosb, sinb,
                                                   qf, kf, vf);
    }
    // 3) Flash attention (128-q tiles, double-buffered KV)
    flash_mma<<<dim3(SS / 128, NQ, BB), 256, FA_SMEM>>>(qf, kf, vf, ath, atl);
    // 4) Output projection (fp16x2)
    gemm_f16x2<<<dim3(HH / 256, M / 128), 256, GEMM_SMEM>>>(
        ath, atl, wo, out, M, HH, HH);
}

// round 14
// speedup vs baseline: 1.0293x; 1.0293x over previous
#include <cuda_runtime.h>
#include <cuda_bf16.h>
#include <cuda_fp16.h>
#include <math.h>
#include <stdint.h>

// Problem constants
#define BB   2
#define SS   1024
#define PP   1024
#define TT   (PP + SS)
#define HH   4096
#define NQ   32
#define NKV  8
#define DD   128
#define QKVN ((NQ + 2 * NKV) * DD)   // 6144
#define SCALE 0.08838834764831845f   // 1/sqrt(128)

// ---------------------------------------------------------------------------
// Scratch (device globals: no allocation allowed)
// ---------------------------------------------------------------------------
__device__ float g_qkv[BB * SS * QKVN];
__device__ __half g_hid[BB * SS * HH];
__device__ __half g_wqkv[(size_t)QKVN * HH];         // transposed [N,K]
__device__ __half g_wo[(size_t)HH * HH];             // transposed [N,K]
__device__ __half g_attn_h[BB * SS * NQ * DD];
__device__ __half g_attn_l[BB * SS * NQ * DD];
__device__ __half g_q_f[(size_t)BB * NQ * SS * DD];
__device__ __half g_k_f[(size_t)BB * NKV * TT * DD];
__device__ __half g_v_f[(size_t)BB * NKV * TT * DD];

// ---------------------------------------------------------------------------
// Low-level helpers (plain sm_80+ ISA)
// ---------------------------------------------------------------------------
__device__ __forceinline__ uint32_t smem_u32(const void* p) {
    uint32_t a;
    asm("{ .reg .u64 t; cvta.to.shared.u64 t, %1; cvt.u32.u64 %0, t; }"
        : "=r"(a) : "l"(p));
    return a;
}
__device__ __forceinline__ void cp16(uint32_t dst, const void* src) {
    asm volatile("cp.async.cg.shared.global [%0], [%1], 16;"
                 :: "r"(dst), "l"(src));
}
__device__ __forceinline__ void ldsm4(uint32_t* r, uint32_t a) {
    asm volatile("ldmatrix.sync.aligned.m8n8.x4.shared.b16 {%0,%1,%2,%3}, [%4];"
                 : "=r"(r[0]), "=r"(r[1]), "=r"(r[2]), "=r"(r[3]) : "r"(a));
}
__device__ __forceinline__ void ldsm4t(uint32_t* r, uint32_t a) {
    asm volatile("ldmatrix.sync.aligned.m8n8.x4.trans.shared.b16 {%0,%1,%2,%3}, [%4];"
                 : "=r"(r[0]), "=r"(r[1]), "=r"(r[2]), "=r"(r[3]) : "r"(a));
}
__device__ __forceinline__ void mma16816h(float* c, const uint32_t* a,
                                          const uint32_t b0, const uint32_t b1) {
    asm volatile(
        "mma.sync.aligned.m16n8k16.row.col.f32.f16.f16.f32 "
        "{%0,%1,%2,%3}, {%4,%5,%6,%7}, {%8,%9}, {%0,%1,%2,%3};"
        : "+f"(c[0]), "+f"(c[1]), "+f"(c[2]), "+f"(c[3])
        : "r"(a[0]), "r"(a[1]), "r"(a[2]), "r"(a[3]), "r"(b0), "r"(b1));
}

// ---------------------------------------------------------------------------
// fp32 -> fp16 convert (GEMM1 activations)
// ---------------------------------------------------------------------------
__global__ void conv_f16(const float* __restrict__ x,
                         __half* __restrict__ xo, int n)
{
    int i = blockIdx.x * blockDim.x + threadIdx.x;
    if (i >= n) return;
    xo[i] = __float2half(x[i]);
}

// fp32 [R,C] -> fp16 transposed [C,R] (weights)
__global__ void trans_f16(const float* __restrict__ x,
                          __half* __restrict__ xo, int R, int C)
{
    __shared__ float t[32][33];
    int r0 = blockIdx.y * 32, c0 = blockIdx.x * 32;
    int tx = threadIdx.x, ty = threadIdx.y;
#pragma unroll
    for (int j = 0; j < 4; j++)
        t[ty + 8 * j][tx] = x[(size_t)(r0 + ty + 8 * j) * C + c0 + tx];
    __syncthreads();
#pragma unroll
    for (int j = 0; j < 4; j++)
        xo[(size_t)(c0 + ty + 8 * j) * R + r0 + tx] = __float2half(t[tx][ty + 8 * j]);
}

// ---------------------------------------------------------------------------
// fp16 single-pass GEMM (QKV): 128x256x64, 8 warps, 3-stage pipeline,
// register-double-buffered fragments (round-12 champion config).
// ---------------------------------------------------------------------------
#define X1_A_OFF 0
#define X1_B_OFF 16384
#define X1_STAGE 49152
#define GEMM1_SMEM (3 * X1_STAGE)

#define LOAD_STAGE1(c, s) do {                                             \
    int _k0 = (c) * 64;                                                    \
    uint32_t _stb = smb + (s) * X1_STAGE;                                  \
    _Pragma("unroll")                                                      \
    for (int _i = 0; _i < 4; _i++) {                                       \
        int _id = tid + _i * 256;                                          \
        int _row = _id >> 3, _ch = _id & 7;                                \
        uint32_t _sw = (_row << 7) + ((_ch ^ (_row & 7)) << 4);            \
        cp16(_stb + X1_A_OFF + _sw, srcA + (size_t)_row * K + _k0 + _ch * 8); \
    }                                                                      \
    _Pragma("unroll")                                                      \
    for (int _i = 0; _i < 8; _i++) {                                       \
        int _id = tid + _i * 256;                                          \
        int _row = _id >> 3, _ch = _id & 7;                                \
        uint32_t _sw = (_row << 7) + ((_ch ^ (_row & 7)) << 4);            \
        cp16(_stb + X1_B_OFF + _sw, srcB + (size_t)_row * K + _k0 + _ch * 8); \
    }                                                                      \
    asm volatile("cp.async.commit_group;");                                \
} while (0)

__global__ __launch_bounds__(256, 1) void gemm_f16x1(
    const __half* __restrict__ A, const __half* __restrict__ B,
    float* __restrict__ C, int M, int N, int K)
{
    extern __shared__ char sm[];
    const uint32_t smb = smem_u32(sm);
    const int tid = threadIdx.x;
    const int wid = tid >> 5, lane = tid & 31;
    const int bm = blockIdx.y * 128, bn = blockIdx.x * 256;
    const int wm = (wid & 1) * 64, wn = (wid >> 1) * 64;

    const __half* srcA = A + (size_t)bm * K;
    const __half* srcB = B + (size_t)bn * K;

    uint32_t arb[4], brb[4];
    int rswA[4], rswB[4];
#pragma unroll
    for (int mi = 0; mi < 4; mi++) {
        int row = wm + mi * 16 + (lane & 15);
        arb[mi] = (uint32_t)(row << 7) + X1_A_OFF;
        rswA[mi] = row & 7;
    }
#pragma unroll
    for (int ni = 0; ni < 4; ni++) {
        int row = wn + ni * 16 + (lane & 15);
        brb[ni] = (uint32_t)(row << 7) + X1_B_OFF;
        rswB[ni] = row & 7;
    }

    float acc[4][8][4];
#pragma unroll
    for (int i = 0; i < 4; i++)
#pragma unroll
        for (int j = 0; j < 8; j++)
#pragma unroll
            for (int e = 0; e < 4; e++) acc[i][j][e] = 0.f;

    const int NC = K / 64;
    LOAD_STAGE1(0, 0);
    LOAD_STAGE1(1, 1);

    uint32_t ah[2][4][4], bh[2][4][4];
    int sc = 0, sl = 2;
    for (int c = 0; c < NC; c++) {
        __syncthreads();
        if (c + 2 < NC) {
            LOAD_STAGE1(c + 2, sl);
            asm volatile("cp.async.wait_group 2;");
        } else if (c + 1 < NC) {
            asm volatile("cp.async.wait_group 1;");
        } else {
            asm volatile("cp.async.wait_group 0;");
        }
        __syncthreads();

        const uint32_t base = smb + sc * X1_STAGE;
        {
            const int c0 = (lane >> 4);
#pragma unroll
            for (int mi = 0; mi < 4; mi++)
                ldsm4(ah[0][mi], base + arb[mi] + ((c0 ^ rswA[mi]) << 4));
#pragma unroll
            for (int ni = 0; ni < 4; ni++)
                ldsm4(bh[0][ni], base + brb[ni] + ((c0 ^ rswB[ni]) << 4));
        }
#pragma unroll
        for (int ks = 0; ks < 4; ks++) {
            const int cur = ks & 1, nxt = cur ^ 1;
            if (ks < 3) {
                const int c0 = (ks + 1) * 2 + (lane >> 4);
#pragma unroll
                for (int mi = 0; mi < 4; mi++)
                    ldsm4(ah[nxt][mi], base + arb[mi] + ((c0 ^ rswA[mi]) << 4));
#pragma unroll
                for (int ni = 0; ni < 4; ni++)
                    ldsm4(bh[nxt][ni], base + brb[ni] + ((c0 ^ rswB[ni]) << 4));
            }
#pragma unroll
            for (int mi = 0; mi < 4; mi++)
#pragma unroll
                for (int ni = 0; ni < 4; ni++)
#pragma unroll
                    for (int sel = 0; sel < 2; sel++)
                        mma16816h(acc[mi][ni * 2 + sel], ah[cur][mi],
                                  bh[cur][ni][sel], bh[cur][ni][sel + 2]);
        }
        sc = (sc == 2) ? 0 : sc + 1;
        sl = (sl == 2) ? 0 : sl + 1;
    }

    const int g = lane >> 2, t = lane & 3;
#pragma unroll
    for (int mi = 0; mi < 4; mi++) {
#pragma unroll
        for (int nj = 0; nj < 8; nj++) {
            const float* a = acc[mi][nj];
            int row = bm + wm + mi * 16 + g;
            int col = bn + wn + nj * 8 + t * 2;
            *(float2*)&C[(size_t)row * N + col] = make_float2(a[0], a[1]);
            *(float2*)&C[(size_t)(row + 8) * N + col] = make_float2(a[2], a[3]);
        }
    }
}

// ---------------------------------------------------------------------------
// fp16x2 GEMM (output projection) — round-12 version.
// ---------------------------------------------------------------------------
#define AH_OFF 0
#define AL_OFF 16384
#define BH_OFF 32768
#define STAGE_B  65536
#define GEMM_SMEM (3 * STAGE_B)

#define LOAD_STAGE(c, s) do {                                              \
    int _k0 = (c) * 64;                                                    \
    uint32_t _stb = smb + (s) * STAGE_B;                                   \
    _Pragma("unroll")                                                      \
    for (int _i = 0; _i < 4; _i++) {                                       \
        int _id = tid + _i * 256;                                          \
        int _row = _id >> 3, _ch = _id & 7;                                \
        uint32_t _sw = (_row << 7) + ((_ch ^ (_row & 7)) << 4);            \
        const size_t _go = (size_t)_row * K + _k0 + _ch * 8;               \
        cp16(_stb + AH_OFF + _sw, srcAh + _go);                            \
        cp16(_stb + AL_OFF + _sw, srcAl + _go);                            \
    }                                                                      \
    _Pragma("unroll")                                                      \
    for (int _i = 0; _i < 8; _i++) {                                       \
        int _id = tid + _i * 256;                                          \
        int _row = _id >> 3, _ch = _id & 7;                                \
        uint32_t _sw = (_row << 7) + ((_ch ^ (_row & 7)) << 4);            \
        cp16(_stb + BH_OFF + _sw, srcB + (size_t)_row * K + _k0 + _ch * 8); \
    }                                                                      \
    asm volatile("cp.async.commit_group;");                                \
} while (0)

__global__ __launch_bounds__(256, 1) void gemm_f16x2(
    const __half* __restrict__ Ah, const __half* __restrict__ Al,
    const __half* __restrict__ B,
    float* __restrict__ C, int M, int N, int K)
{
    extern __shared__ char sm[];
    const uint32_t smb = smem_u32(sm);
    const int tid = threadIdx.x;
    const int wid = tid >> 5, lane = tid & 31;
    const int bm = blockIdx.y * 128, bn = blockIdx.x * 256;
    const int wm = (wid & 1) * 64, wn = (wid >> 1) * 64;

    const __half* srcAh = Ah + (size_t)bm * K;
    const __half* srcAl = Al + (size_t)bm * K;
    const __half* srcB  = B  + (size_t)bn * K;

    uint32_t arb[4], brb[4];
    int rswA[4], rswB[4];
#pragma unroll
    for (int mi = 0; mi < 4; mi++) {
        int row = wm + mi * 16 + (lane & 15);
        arb[mi] = (uint32_t)(row << 7);
        rswA[mi] = row & 7;
    }
#pragma unroll
    for (int ni = 0; ni < 4; ni++) {
        int row = wn + ni * 16 + (lane & 15);
        brb[ni] = (uint32_t)(row << 7);
        rswB[ni] = row & 7;
    }

    float acc[4][8][4];
#pragma unroll
    for (int i = 0; i < 4; i++)
#pragma unroll
        for (int j = 0; j < 8; j++)
#pragma unroll
            for (int e = 0; e < 4; e++) acc[i][j][e] = 0.f;

    const int NC = K / 64;
    LOAD_STAGE(0, 0);
    LOAD_STAGE(1, 1);

    uint32_t ah[2][4][4], bh[2][4][4], al[4][4];
    int sc = 0, sl = 2;
    for (int c = 0; c < NC; c++) {
        __syncthreads();
        if (c + 2 < NC) {
            LOAD_STAGE(c + 2, sl);
            asm volatile("cp.async.wait_group 2;");
        } else if (c + 1 < NC) {
            asm volatile("cp.async.wait_group 1;");
        } else {
            asm volatile("cp.async.wait_group 0;");
        }
        __syncthreads();

        const uint32_t base = smb + sc * STAGE_B;
        {
            const int c0 = (lane >> 4);
#pragma unroll
            for (int mi = 0; mi < 4; mi++)
                ldsm4(ah[0][mi], base + AH_OFF + arb[mi] + ((c0 ^ rswA[mi]) << 4));
#pragma unroll
            for (int ni = 0; ni < 4; ni++)
                ldsm4(bh[0][ni], base + BH_OFF + brb[ni] + ((c0 ^ rswB[ni]) << 4));
        }
#pragma unroll
        for (int ks = 0; ks < 4; ks++) {
            const int cur = ks & 1, nxt = cur ^ 1;
            const int c0c = ks * 2 + (lane >> 4);
#pragma unroll
            for (int mi = 0; mi < 4; mi++)
                ldsm4(al[mi], base + AL_OFF + arb[mi] + ((c0c ^ rswA[mi]) << 4));
            if (ks < 3) {
                const int c0n = (ks + 1) * 2 + (lane >> 4);
#pragma unroll
                for (int mi = 0; mi < 4; mi++)
                    ldsm4(ah[nxt][mi], base + AH_OFF + arb[mi] + ((c0n ^ rswA[mi]) << 4));
#pragma unroll
                for (int ni = 0; ni < 4; ni++)
                    ldsm4(bh[nxt][ni], base + BH_OFF + brb[ni] + ((c0n ^ rswB[ni]) << 4));
            }
#pragma unroll
            for (int mi = 0; mi < 4; mi++)
#pragma unroll
                for (int ni = 0; ni < 4; ni++)
#pragma unroll
                    for (int sel = 0; sel < 2; sel++)
                        mma16816h(acc[mi][ni * 2 + sel], ah[cur][mi],
                                  bh[cur][ni][sel], bh[cur][ni][sel + 2]);
#pragma unroll
            for (int mi = 0; mi < 4; mi++)
#pragma unroll
                for (int ni = 0; ni < 4; ni++)
#pragma unroll
                    for (int sel = 0; sel < 2; sel++)
                        mma16816h(acc[mi][ni * 2 + sel], al[mi],
                                  bh[cur][ni][sel], bh[cur][ni][sel + 2]);
        }
        sc = (sc == 2) ? 0 : sc + 1;
        sl = (sl == 2) ? 0 : sl + 1;
    }

    const int g = lane >> 2, t = lane & 3;
#pragma unroll
    for (int mi = 0; mi < 4; mi++) {
#pragma unroll
        for (int nj = 0; nj < 8; nj++) {
            const float* a = acc[mi][nj];
            int row = bm + wm + mi * 16 + g;
            int col = bn + wn + nj * 8 + t * 2;
            *(float2*)&C[(size_t)row * N + col] = make_float2(a[0], a[1]);
            *(float2*)&C[(size_t)(row + 8) * N + col] = make_float2(a[2], a[3]);
        }
    }
}

// ---------------------------------------------------------------------------
// Fused pre-pass (unchanged arithmetic)
// ---------------------------------------------------------------------------
#define NQTOT (BB * SS * NQ * 64)
#define KVTOT (BB * NKV * TT * 64)

__global__ void prep_qkv_f16(const float* __restrict__ qkv,
                             const float* __restrict__ kcache,
                             const float* __restrict__ vcache,
                             const float* __restrict__ cosb,
                             const float* __restrict__ sinb,
                             __half* __restrict__ qf,
                             __half* __restrict__ kf, __half* __restrict__ vf)
{
    int idx = blockIdx.x * blockDim.x + threadIdx.x;
    if (idx < NQTOT) {
        int d = idx & 63;
        int rest = idx >> 6;
        int h = rest % NQ;
        int s = (rest / NQ) % SS;
        int b = rest / (NQ * SS);
        const float* base = &qkv[((size_t)(b * SS + s)) * QKVN + h * DD];
        float x1 = base[d], x2 = base[d + 64];
        float c0 = cosb[s * DD + d],      s0 = sinb[s * DD + d];
        float c1 = cosb[s * DD + d + 64], s1 = sinb[s * DD + d + 64];
        size_t o = (((size_t)(b * NQ + h)) * SS + s) * DD + d;
        qf[o]      = __float2half((x1 * c0 - x2 * s0) * SCALE);
        qf[o + 64] = __float2half((x2 * c1 + x1 * s1) * SCALE);
        return;
    }
    idx -= NQTOT;
    if (idx >= KVTOT) return;
    int d = idx & 63;
    int rest = idx >> 6;
    int t = rest % TT;
    int kh = (rest / TT) % NKV;
    int b = rest / (TT * NKV);

    float k1, k2, v1, v2;
    if (t < PP) {
        size_t src = (((size_t)(b * PP + t)) * NKV + kh) * DD;
        k1 = kcache[src + d]; k2 = kcache[src + d + 64];
        v1 = vcache[src + d]; v2 = vcache[src + d + 64];
    } else {
        int s = t - PP;
        const float* base = &qkv[((size_t)(b * SS + s)) * QKVN];
        float x1 = base[(NQ + kh) * DD + d], x2 = base[(NQ + kh) * DD + d + 64];
        float c0 = cosb[s * DD + d],      s0 = sinb[s * DD + d];
        float c1 = cosb[s * DD + d + 64], s1 = sinb[s * DD + d + 64];
        k1 = x1 * c0 - x2 * s0;
        k2 = x2 * c1 + x1 * s1;
        v1 = base[(NQ + NKV + kh) * DD + d];
        v2 = base[(NQ + NKV + kh) * DD + d + 64];
    }
    size_t o = (((size_t)(b * NKV + kh)) * TT + t) * DD + d;
    kf[o]      = __float2half(k1);
    kf[o + 64] = __float2half(k2);
    vf[o]      = __float2half(v1);
    vf[o + 64] = __float2half(v2);
}

// ---------------------------------------------------------------------------
// Flash attention: 64-q tile, 4 warps (round-12 shape), NOW with
// double-buffered KV tiles (prefetch kt+1 during compute of kt).
// ---------------------------------------------------------------------------
#define FA_SMEM (2 * 32768)   // 2 buffers x (K 16KB + V 16KB)

#define FLOADKV(kt, bsel) do {                                               \
    const __half* _srcK = kf_g + kvb + (size_t)(kt) * 64 * DD;               \
    const __half* _srcV = vf_g + kvb + (size_t)(kt) * 64 * DD;               \
    uint32_t _kb = smb + (bsel) * 32768;                                     \
    _Pragma("unroll")                                                        \
    for (int _i = 0; _i < 8; _i++) {                                         \
        int _id = tid + _i * 128;                                            \
        int _r = _id >> 4, _ch = _id & 15;                                   \
        uint32_t _sw = _r * 256 + ((_ch ^ (_r & 7)) << 4);                   \
        cp16(_kb + _sw,         _srcK + _r * DD + _ch * 8);                  \
        cp16(_kb + 16384 + _sw, _srcV + _r * DD + _ch * 8);                  \
    }                                                                        \
    asm volatile("cp.async.commit_group;");                                  \
} while (0)

__global__ __launch_bounds__(128) void flash_mma(
    const __half* __restrict__ qf_g,
    const __half* __restrict__ kf_g,
    const __half* __restrict__ vf_g,
    __half* __restrict__ attnh, __half* __restrict__ attnl)
{
    extern __shared__ char sm[];
    const uint32_t smb = smem_u32(sm);
    const int tid = threadIdx.x, lane = tid & 31, w = tid >> 5;
    const int qi = blockIdx.x, h = blockIdx.y, b = blockIdx.z;
    const int sq0 = qi * 64;
    const int khd = h >> 2;
    const int g = lane >> 2, t4 = lane & 3;
    const int r0 = w * 16 + g, r1 = r0 + 8;

    uint32_t qf[8][4];
    {
        const __half* qb = qf_g + (((size_t)(b * NQ + h)) * SS + sq0) * DD;
#pragma unroll
        for (int ks = 0; ks < 8; ks++) {
            int c0 = ks * 16 + 2 * t4;
            qf[ks][0] = *(const uint32_t*)(qb + r0 * DD + c0);
            qf[ks][1] = *(const uint32_t*)(qb + r1 * DD + c0);
            qf[ks][2] = *(const uint32_t*)(qb + r0 * DD + c0 + 8);
            qf[ks][3] = *(const uint32_t*)(qb + r1 * DD + c0 + 8);
        }
    }

    uint32_t krb[4];
    int krsw[4];
#pragma unroll
    for (int kg = 0; kg < 4; kg++) {
        int r = kg * 16 + (lane & 15);
        krb[kg] = (uint32_t)(r * 256);
        krsw[kg] = r & 7;
    }

    float oacc[16][4];
#pragma unroll
    for (int i = 0; i < 16; i++)
#pragma unroll
        for (int j = 0; j < 4; j++) oacc[i][j] = 0.f;
    float m0 = -1e30f, m1 = -1e30f, l0 = 0.f, l1 = 0.f;

    const size_t kvb = ((size_t)(b * NKV + khd)) * TT * DD;
    const int nt = qi + 1 + PP / 64;

    FLOADKV(0, 0);

    for (int kt = 0; kt < nt; kt++) {
        const int bf = kt & 1;
        if (kt + 1 < nt) {
            FLOADKV(kt + 1, bf ^ 1);
            asm volatile("cp.async.wait_group 1;");
        } else {
            asm volatile("cp.async.wait_group 0;");
        }
        __syncthreads();

        const uint32_t KB = smb + bf * 32768;
        const uint32_t VB = KB + 16384;

        // S = Q K^T with K-fragment double buffering
        float sacc[8][4];
#pragma unroll
        for (int j = 0; j < 8; j++)
#pragma unroll
            for (int e = 0; e < 4; e++) sacc[j][e] = 0.f;

        uint32_t kb[2][4][4];
        {
            const int c0 = (lane >> 4);
#pragma unroll
            for (int kg = 0; kg < 4; kg++)
                ldsm4(kb[0][kg], KB + krb[kg] + ((c0 ^ krsw[kg]) << 4));
        }
#pragma unroll
        for (int ks = 0; ks < 8; ks++) {
            const int cur = ks & 1, nxt = cur ^ 1;
            if (ks < 7) {
                const int c0 = (ks + 1) * 2 + (lane >> 4);
#pragma unroll
                for (int kg = 0; kg < 4; kg++)
                    ldsm4(kb[nxt][kg], KB + krb[kg] + ((c0 ^ krsw[kg]) << 4));
            }
#pragma unroll
            for (int kg = 0; kg < 4; kg++)
#pragma unroll
                for (int sel = 0; sel < 2; sel++)
                    mma16816h(sacc[kg * 2 + sel], qf[ks],
                              kb[cur][kg][sel], kb[cur][kg][sel + 2]);
        }

        if (kt == nt - 1) {
#pragma unroll
            for (int j = 0; j < 8; j++) {
                int cb = j * 8 + 2 * t4;
                if (cb     > r0) sacc[j][0] = -1e30f;
                if (cb + 1 > r0) sacc[j][1] = -1e30f;
                if (cb     > r1) sacc[j][2] = -1e30f;
                if (cb + 1 > r1) sacc[j][3] = -1e30f;
            }
        }

        float mx0 = m0, mx1 = m1;
#pragma unroll
        for (int j = 0; j < 8; j++) {
            mx0 = fmaxf(mx0, fmaxf(sacc[j][0], sacc[j][1]));
            mx1 = fmaxf(mx1, fmaxf(sacc[j][2], sacc[j][3]));
        }
        mx0 = fmaxf(mx0, __shfl_xor_sync(0xffffffff, mx0, 1));
        mx0 = fmaxf(mx0, __shfl_xor_sync(0xffffffff, mx0, 2));
        mx1 = fmaxf(mx1, __shfl_xor_sync(0xffffffff, mx1, 1));
        mx1 = fmaxf(mx1, __shfl_xor_sync(0xffffffff, mx1, 2));
        float rs0 = __expf(m0 - mx0), rs1 = __expf(m1 - mx1);
        m0 = mx0; m1 = mx1;
        l0 *= rs0; l1 *= rs1;

        uint32_t pf[4][4];
#pragma unroll
        for (int j = 0; j < 8; j++) {
            float p0 = __expf(sacc[j][0] - m0);
            float p1 = __expf(sacc[j][1] - m0);
            float p2 = __expf(sacc[j][2] - m1);
            float p3 = __expf(sacc[j][3] - m1);
            l0 += p0 + p1; l1 += p2 + p3;
            int kk = j >> 1, u = (j & 1) * 2;
            __half2 hA = __float22half2_rn(make_float2(p0, p1));
            __half2 hB = __float22half2_rn(make_float2(p2, p3));
            pf[kk][u]     = *(uint32_t*)&hA;
            pf[kk][u + 1] = *(uint32_t*)&hB;
        }

#pragma unroll
        for (int i = 0; i < 16; i++) {
            oacc[i][0] *= rs0; oacc[i][1] *= rs0;
            oacc[i][2] *= rs1; oacc[i][3] *= rs1;
        }

        // O += P V with V-fragment double buffering
        uint32_t vfr[2][2][4];
        {
            int r = (lane & 15);
            int cA = (lane >> 4);
            int cB = 2 + (lane >> 4);
            ldsm4t(vfr[0][0], VB + r * 256 + ((cA ^ (r & 7)) << 4));
            ldsm4t(vfr[0][1], VB + r * 256 + ((cB ^ (r & 7)) << 4));
        }
#pragma unroll
        for (int idx = 0; idx < 16; idx++) {
            const int cur = idx & 1, nxt = cur ^ 1;
            const int kk = idx >> 2, dp = idx & 3;
            if (idx < 15) {
                const int kk2 = (idx + 1) >> 2, dp2 = (idx + 1) & 3;
                int r = kk2 * 16 + (lane & 15);
                int cA = dp2 * 4 + (lane >> 4);
                int cB = dp2 * 4 + 2 + (lane >> 4);
                ldsm4t(vfr[nxt][0], VB + r * 256 + ((cA ^ (r & 7)) << 4));
                ldsm4t(vfr[nxt][1], VB + r * 256 + ((cB ^ (r & 7)) << 4));
            }
            const int dg0 = dp * 2, dg1 = dp * 2 + 1;
            mma16816h(oacc[dg0 * 2],     pf[kk], vfr[cur][0][0], vfr[cur][0][1]);
            mma16816h(oacc[dg0 * 2 + 1], pf[kk], vfr[cur][0][2], vfr[cur][0][3]);
            mma16816h(oacc[dg1 * 2],     pf[kk], vfr[cur][1][0], vfr[cur][1][1]);
            mma16816h(oacc[dg1 * 2 + 1], pf[kk], vfr[cur][1][2], vfr[cur][1][3]);
        }
        __syncthreads();   // all warps done with buffer bf before it is reloaded
    }

    l0 += __shfl_xor_sync(0xffffffff, l0, 1);
    l0 += __shfl_xor_sync(0xffffffff, l0, 2);
    l1 += __shfl_xor_sync(0xffffffff, l1, 1);
    l1 += __shfl_xor_sync(0xffffffff, l1, 2);
    float inv0 = 1.f / l0, inv1 = 1.f / l1;

    size_t rowA = ((size_t)(b * SS + sq0 + r0)) * (NQ * DD) + h * DD;
    size_t rowB = ((size_t)(b * SS + sq0 + r1)) * (NQ * DD) + h * DD;
#pragma unroll
    for (int dt = 0; dt < 16; dt++) {
        int c = dt * 8 + 2 * t4;
        float v0 = oacc[dt][0] * inv0, v1 = oacc[dt][1] * inv0;
        float v2 = oacc[dt][2] * inv1, v3 = oacc[dt][3] * inv1;
        __half2 hA = __float22half2_rn(make_float2(v0, v1));
        float2 fA = __half22float2(hA);
        __half2 lA = __float22half2_rn(make_float2(v0 - fA.x, v1 - fA.y));
        __half2 hB = __float22half2_rn(make_float2(v2, v3));
        float2 fB = __half22float2(hB);
        __half2 lB = __float22half2_rn(make_float2(v2 - fB.x, v3 - fB.y));
        *(__half2*)&attnh[rowA + c] = hA;
        *(__half2*)&attnl[rowA + c] = lA;
        *(__half2*)&attnh[rowB + c] = hB;
        *(__half2*)&attnl[rowB + c] = lB;
    }
}

// ---------------------------------------------------------------------------
extern "C" void kernel_launch(void* const* d_in, const int* in_sizes, int n_in,
                              void* d_out, int out_size)
{
    const float* hidden = (const float*)d_in[0];
    const float* w_qkv  = (const float*)d_in[1];
    const float* w_o    = (const float*)d_in[2];
    const float* cosb   = (const float*)d_in[3];
    const float* sinb   = (const float*)d_in[4];
    const float* kc     = (const float*)d_in[5];
    const float* vc     = (const float*)d_in[6];
    float* out = (float*)d_out;

    float *qkv;
    __half *hidf, *wq, *wo, *ath, *atl, *qf, *kf, *vf;
    cudaGetSymbolAddress((void**)&qkv, g_qkv);
    cudaGetSymbolAddress((void**)&hidf, g_hid);
    cudaGetSymbolAddress((void**)&wq, g_wqkv);
    cudaGetSymbolAddress((void**)&wo, g_wo);
    cudaGetSymbolAddress((void**)&ath, g_attn_h);
    cudaGetSymbolAddress((void**)&atl, g_attn_l);
    cudaGetSymbolAddress((void**)&qf, g_q_f);
    cudaGetSymbolAddress((void**)&kf, g_k_f);
    cudaGetSymbolAddress((void**)&vf, g_v_f);

    cudaFuncSetAttribute(gemm_f16x1,
                         cudaFuncAttributeMaxDynamicSharedMemorySize, GEMM1_SMEM);
    cudaFuncSetAttribute(gemm_f16x2,
                         cudaFuncAttributeMaxDynamicSharedMemorySize, GEMM_SMEM);
    cudaFuncSetAttribute(flash_mma,
                         cudaFuncAttributeMaxDynamicSharedMemorySize, FA_SMEM);

    const int M = BB * SS;  // 2048

    // 0) activation convert + weight transposes
    {
        int n = M * HH;
        conv_f16<<<(n + 255) / 256, 256>>>(hidden, hidf, n);
        trans_f16<<<dim3(QKVN / 32, HH / 32), dim3(32, 8)>>>(w_qkv, wq, HH, QKVN);
        trans_f16<<<dim3(HH / 32, HH / 32), dim3(32, 8)>>>(w_o, wo, HH, HH);
    }
    // 1) QKV projection (fp16 single-pass)
    gemm_f16x1<<<dim3(QKVN / 256, M / 128), 256, GEMM1_SMEM>>>(
        hidf, wq, qkv, M, QKVN, HH);
    // 2) fused pre-pass
    {
        int total = NQTOT + KVTOT;
        prep_qkv_f16<<<(total + 255) / 256, 256>>>(qkv, kc, vc, cosb, sinb,
                                                   qf, kf, vf);
    }
    // 3) Flash attention (64-q tiles, double-buffered KV)
    flash_mma<<<dim3(SS / 64, NQ, BB), 128, FA_SMEM>>>(qf, kf, vf, ath, atl);
    // 4) Output projection (fp16x2)
    gemm_f16x2<<<dim3(HH / 256, M / 128), 256, GEMM_SMEM>>>(
        ath, atl, wo, out, M, HH, HH);
}